// round 3
// baseline (speedup 1.0000x reference)
#include <cuda_runtime.h>

#define N_NODE 50000
#define N_EDGE 800000
#define D_FEAT 64
#define N_M    11
#define DEPTH  3

// ---------------- device scratch (no allocations allowed) ----------------
__device__ float    g_y[2][N_NODE * D_FEAT];   // S x, S^2 x (S^3 x fused into output)
__device__ float    g_dinv[N_NODE];
__device__ unsigned g_cnt[N_NODE];             // counts, then reused as fill cursors
__device__ unsigned g_rowstart[N_NODE + 1];
__device__ int      g_colS[N_EDGE];            // CSR: cols sorted by row
__device__ float    g_valS[N_EDGE];            // CSR: normalized edge weights
__device__ float    g_q[16];                   // q[L][k]

// ---------------- zero counters ----------------
__global__ __launch_bounds__(256) void zero_cnt_kernel() {
    unsigned i = blockIdx.x * blockDim.x + threadIdx.x;
    if (i < N_NODE) g_cnt[i] = 0u;
}

// ---------------- polynomial coefficient table ----------------
// xs_hist[L][m] = sum_k p[L][m][k] * S^k x  (recurrence is linear in S, xs0==x).
// l=-1, r=1 so (l+r)=0, (r-l)=2.
__global__ void coeff_kernel(const float* __restrict__ alphas,
                             const float* __restrict__ w,
                             const float* __restrict__ a_arr,
                             const float* __restrict__ b_arr) {
    if (threadIdx.x != 0 || blockIdx.x != 0) return;
    double q[4][4] = {};
    for (int m = 0; m < N_M; m++) {
        double a = a_arr[m], b = b_arr[m];
        double p[4][4] = {};
        p[0][0] = 1.0;
        double coef1 = (a - b) * 0.5;
        double coef2 = (a + b + 2.0) * 0.5;
        double al0 = alphas[0 * N_M + m];
        p[1][0] = al0 * coef1;
        p[1][1] = al0 * coef2;
        for (int L = 2; L <= DEPTH; L++) {
            double Lf = (double)L;
            double coef_l  = 2.0 * Lf * (Lf + a + b) * (2.0 * Lf - 2.0 + a + b);
            double c_lm1_1 = (2.0 * Lf + a + b - 1.0) * (2.0 * Lf + a + b) * (2.0 * Lf + a + b - 2.0);
            double c_lm1_2 = (2.0 * Lf + a + b - 1.0) * (a * a - b * b);
            double c_lm2   = 2.0 * (Lf - 1.0 + a) * (Lf - 1.0 + b) * (2.0 * Lf + a + b);
            double alL   = alphas[(L - 1) * N_M + m];
            double alLm1 = alphas[(L - 2) * N_M + m];
            double tmp1 = alL * (c_lm1_1 / coef_l);
            double tmp2 = alL * (c_lm1_2 / coef_l);
            double tmp3 = alL * alLm1 * (c_lm2 / coef_l);
            for (int k = 0; k <= L; k++) {
                double t = 0.0;
                if (k > 0) t += tmp1 * p[L - 1][k - 1];
                t -= tmp2 * p[L - 1][k];
                t -= tmp3 * p[L - 2][k];
                p[L][k] = t;
            }
        }
        double wm = w[m];
        for (int L = 0; L < 4; L++)
            for (int k = 0; k < 4; k++)
                q[L][k] += wm * p[L][k];
    }
    for (int i = 0; i < 16; i++) g_q[i] = (float)q[i / 4][i % 4];
}

// ---------------- per-row edge counts ----------------
__global__ __launch_bounds__(256) void count_kernel(const int* __restrict__ ei) {
    unsigned e = blockIdx.x * blockDim.x + threadIdx.x;
    if (e < N_EDGE) atomicAdd(&g_cnt[ei[e]], 1u);
}

// ---------------- single-block exclusive scan + dinv + reset counters ----------------
__global__ __launch_bounds__(1024) void scan_kernel() {
    __shared__ unsigned ssum[1024];
    const int T = 1024;
    int t = threadIdx.x;
    const int PER = (N_NODE + T - 1) / T;   // 49
    int base = t * PER;
    unsigned local = 0;
    for (int i = 0; i < PER; i++) {
        int n = base + i;
        if (n < N_NODE) local += g_cnt[n];
    }
    ssum[t] = local;
    __syncthreads();
    // Hillis-Steele inclusive scan
    for (int off = 1; off < T; off <<= 1) {
        unsigned v = (t >= off) ? ssum[t - off] : 0u;
        __syncthreads();
        ssum[t] += v;
        __syncthreads();
    }
    unsigned run = (t == 0) ? 0u : ssum[t - 1];
    for (int i = 0; i < PER; i++) {
        int n = base + i;
        if (n < N_NODE) {
            g_rowstart[n] = run;
            unsigned c = g_cnt[n];
            run += c;
            g_dinv[n] = rsqrtf(c ? (float)c : 1.0f);
            g_cnt[n] = 0u;   // reuse as fill cursor
        }
    }
    if (t == T - 1) g_rowstart[N_NODE] = run;
}

// ---------------- scatter edges into CSR, computing normalized weights ----------------
__global__ __launch_bounds__(256) void scatter_kernel(const int* __restrict__ ei,
                                                       const float* __restrict__ attr) {
    unsigned e = blockIdx.x * blockDim.x + threadIdx.x;
    if (e >= N_EDGE) return;
    int r = ei[e];
    int c = ei[e + N_EDGE];
    float v = g_dinv[r] * attr[e] * g_dinv[c];
    unsigned pos = g_rowstart[r] + atomicAdd(&g_cnt[r], 1u);
    g_colS[pos] = c;
    g_valS[pos] = v;
}

// ---------------- CSR SpMM: 16 threads per row, float4 per thread ----------------
// stage 0: x -> g_y[0];  stage 1: g_y[0] -> g_y[1].
// All scratch pointers are resolved IN DEVICE CODE (passing __device__ globals
// as host-side kernel args resolves to the host shadow symbol -> garbage).
__global__ __launch_bounds__(256) void spmm_csr_kernel(const float4* __restrict__ xext,
                                                        int stage) {
    unsigned gid = blockIdx.x * blockDim.x + threadIdx.x;
    unsigned row = gid >> 4;
    if (row >= N_NODE) return;
    unsigned lane = gid & 15u;
    const float4* __restrict__ xin =
        (stage == 0) ? xext : (const float4*)g_y[0];
    float4* yout = (float4*)g_y[stage];

    unsigned s = g_rowstart[row], e = g_rowstart[row + 1];
    float4 acc = {0.f, 0.f, 0.f, 0.f};
    for (unsigned i = s; i < e; i++) {
        int   c = __ldg(g_colS + i);
        float v = __ldg(g_valS + i);
        float4 xv = __ldg(xin + (unsigned)c * 16u + lane);
        acc.x += v * xv.x; acc.y += v * xv.y;
        acc.z += v * xv.z; acc.w += v * xv.w;
    }
    yout[row * 16u + lane] = acc;
}

// ---------------- final CSR SpMM (S^3 x) fused with output combine ----------------
// out[n,L,:] = sum_k q[L][k] * (S^k x)[n,:],  out shape (N_NODE, 4, 64) f32
__global__ __launch_bounds__(256) void spmm_final_kernel(const float4* __restrict__ x,
                                                          float4* __restrict__ out) {
    unsigned gid = blockIdx.x * blockDim.x + threadIdx.x;
    unsigned row = gid >> 4;
    if (row >= N_NODE) return;
    unsigned lane = gid & 15u;
    unsigned s = g_rowstart[row], e = g_rowstart[row + 1];
    const float4* __restrict__ y1 = (const float4*)g_y[1];   // S^2 x (input to this pass)
    float4 a3 = {0.f, 0.f, 0.f, 0.f};                        // S^3 x
    for (unsigned i = s; i < e; i++) {
        int   c = __ldg(g_colS + i);
        float v = __ldg(g_valS + i);
        float4 xv = __ldg(y1 + (unsigned)c * 16u + lane);
        a3.x += v * xv.x; a3.y += v * xv.y;
        a3.z += v * xv.z; a3.w += v * xv.w;
    }

    unsigned idx = row * 16u + lane;
    float4 x0 = __ldg(x + idx);
    float4 a1 = ((const float4*)g_y[0])[idx];
    float4 a2 = ((const float4*)g_y[1])[idx];

    float q00 = g_q[0];
    float q10 = g_q[4],  q11 = g_q[5];
    float q20 = g_q[8],  q21 = g_q[9],  q22 = g_q[10];
    float q30 = g_q[12], q31 = g_q[13], q32 = g_q[14], q33 = g_q[15];

    float4 o0, o1, o2, o3;
    o0.x = q00 * x0.x; o0.y = q00 * x0.y; o0.z = q00 * x0.z; o0.w = q00 * x0.w;

    o1.x = q10 * x0.x + q11 * a1.x;
    o1.y = q10 * x0.y + q11 * a1.y;
    o1.z = q10 * x0.z + q11 * a1.z;
    o1.w = q10 * x0.w + q11 * a1.w;

    o2.x = q20 * x0.x + q21 * a1.x + q22 * a2.x;
    o2.y = q20 * x0.y + q21 * a1.y + q22 * a2.y;
    o2.z = q20 * x0.z + q21 * a1.z + q22 * a2.z;
    o2.w = q20 * x0.w + q21 * a1.w + q22 * a2.w;

    o3.x = q30 * x0.x + q31 * a1.x + q32 * a2.x + q33 * a3.x;
    o3.y = q30 * x0.y + q31 * a1.y + q32 * a2.y + q33 * a3.y;
    o3.z = q30 * x0.z + q31 * a1.z + q32 * a2.z + q33 * a3.z;
    o3.w = q30 * x0.w + q31 * a1.w + q32 * a2.w + q33 * a3.w;

    unsigned base = row * 64u + lane;
    out[base +  0u] = o0;
    out[base + 16u] = o1;
    out[base + 32u] = o2;
    out[base + 48u] = o3;
}

// ---------------- launch ----------------
extern "C" void kernel_launch(void* const* d_in, const int* in_sizes, int n_in,
                              void* d_out, int out_size) {
    const float* x      = (const float*)d_in[0];
    const int*   ei     = (const int*)  d_in[1];
    const float* attr   = (const float*)d_in[2];
    const float* alphas = (const float*)d_in[3];
    const float* w      = (const float*)d_in[4];
    const float* a_arr  = (const float*)d_in[5];
    const float* b_arr  = (const float*)d_in[6];
    float* out = (float*)d_out;

    zero_cnt_kernel<<<(N_NODE + 255) / 256, 256>>>();
    coeff_kernel<<<1, 32>>>(alphas, w, a_arr, b_arr);
    count_kernel<<<(N_EDGE + 255) / 256, 256>>>(ei);
    scan_kernel<<<1, 1024>>>();
    scatter_kernel<<<(N_EDGE + 255) / 256, 256>>>(ei, attr);

    const unsigned rt = (unsigned)N_NODE * 16u;   // 800k threads
    spmm_csr_kernel<<<(rt + 255) / 256, 256>>>((const float4*)x, 0);
    spmm_csr_kernel<<<(rt + 255) / 256, 256>>>((const float4*)x, 1);
    spmm_final_kernel<<<(rt + 255) / 256, 256>>>((const float4*)x, (float4*)out);
}

// round 4
// speedup vs baseline: 1.5023x; 1.5023x over previous
#include <cuda_runtime.h>

#define N_NODE 50000
#define N_EDGE 800000
#define D_FEAT 64
#define N_M    11
#define DEPTH  3

#define SCAN_BLK 512
#define N_SBLK ((N_NODE + SCAN_BLK - 1) / SCAN_BLK)   // 98

// ---------------- device scratch (no allocations allowed) ----------------
__device__ float    g_y[2][N_NODE * D_FEAT];   // S x, S^2 x
__device__ float    g_dinv[N_NODE];
__device__ unsigned g_cnt[N_NODE];             // counts, then reused as fill cursors
__device__ unsigned g_rowstart[N_NODE + 1];
__device__ unsigned g_bsum[N_SBLK];
__device__ int      g_colS[N_EDGE];            // CSR: cols sorted by row
__device__ float    g_valS[N_EDGE];            // CSR: normalized edge weights
__device__ float    g_q[16];                   // q[L][k]

// ---------------- zero counters ----------------
__global__ __launch_bounds__(256) void zero_cnt_kernel() {
    unsigned i = blockIdx.x * blockDim.x + threadIdx.x;
    if (i < N_NODE) g_cnt[i] = 0u;
    if (i == 0) g_rowstart[N_NODE] = N_EDGE;   // total edge count is a constant
}

// ---------------- polynomial coefficient table ----------------
// xs_hist[L][m] = sum_k p[L][m][k] * S^k x  (recurrence linear in S, xs0==x).
// l=-1, r=1 so (l+r)=0, (r-l)=2.
__global__ void coeff_kernel(const float* __restrict__ alphas,
                             const float* __restrict__ w,
                             const float* __restrict__ a_arr,
                             const float* __restrict__ b_arr) {
    if (threadIdx.x != 0 || blockIdx.x != 0) return;
    double q[4][4] = {};
    for (int m = 0; m < N_M; m++) {
        double a = a_arr[m], b = b_arr[m];
        double p[4][4] = {};
        p[0][0] = 1.0;
        double coef1 = (a - b) * 0.5;
        double coef2 = (a + b + 2.0) * 0.5;
        double al0 = alphas[0 * N_M + m];
        p[1][0] = al0 * coef1;
        p[1][1] = al0 * coef2;
        for (int L = 2; L <= DEPTH; L++) {
            double Lf = (double)L;
            double coef_l  = 2.0 * Lf * (Lf + a + b) * (2.0 * Lf - 2.0 + a + b);
            double c_lm1_1 = (2.0 * Lf + a + b - 1.0) * (2.0 * Lf + a + b) * (2.0 * Lf + a + b - 2.0);
            double c_lm1_2 = (2.0 * Lf + a + b - 1.0) * (a * a - b * b);
            double c_lm2   = 2.0 * (Lf - 1.0 + a) * (Lf - 1.0 + b) * (2.0 * Lf + a + b);
            double alL   = alphas[(L - 1) * N_M + m];
            double alLm1 = alphas[(L - 2) * N_M + m];
            double tmp1 = alL * (c_lm1_1 / coef_l);
            double tmp2 = alL * (c_lm1_2 / coef_l);
            double tmp3 = alL * alLm1 * (c_lm2 / coef_l);
            for (int k = 0; k <= L; k++) {
                double t = 0.0;
                if (k > 0) t += tmp1 * p[L - 1][k - 1];
                t -= tmp2 * p[L - 1][k];
                t -= tmp3 * p[L - 2][k];
                p[L][k] = t;
            }
        }
        double wm = w[m];
        for (int L = 0; L < 4; L++)
            for (int k = 0; k < 4; k++)
                q[L][k] += wm * p[L][k];
    }
    for (int i = 0; i < 16; i++) g_q[i] = (float)q[i / 4][i % 4];
}

// ---------------- per-row edge counts ----------------
__global__ __launch_bounds__(256) void count_kernel(const int* __restrict__ ei) {
    unsigned e = blockIdx.x * blockDim.x + threadIdx.x;
    if (e < N_EDGE) atomicAdd(&g_cnt[ei[e]], 1u);
}

// ---------------- two-level exclusive scan: level 1 (per-block) ----------------
__global__ __launch_bounds__(SCAN_BLK) void block_scan_kernel() {
    __shared__ unsigned warp_sums[SCAN_BLK / 32];
    int t = threadIdx.x;
    int i = blockIdx.x * SCAN_BLK + t;
    unsigned v = (i < N_NODE) ? g_cnt[i] : 0u;
    // inclusive warp scan
    unsigned s = v;
    #pragma unroll
    for (int o = 1; o < 32; o <<= 1) {
        unsigned n = __shfl_up_sync(0xffffffffu, s, o);
        if ((t & 31) >= o) s += n;
    }
    if ((t & 31) == 31) warp_sums[t >> 5] = s;
    __syncthreads();
    if (t < SCAN_BLK / 32) {
        unsigned ws = warp_sums[t];
        #pragma unroll
        for (int o = 1; o < SCAN_BLK / 32; o <<= 1) {
            unsigned n = __shfl_up_sync((1u << (SCAN_BLK / 32)) - 1u, ws, o);
            if (t >= o) ws += n;
        }
        warp_sums[t] = ws;
    }
    __syncthreads();
    unsigned base = (t >= 32) ? warp_sums[(t >> 5) - 1] : 0u;
    unsigned incl = base + s;
    if (i < N_NODE) g_rowstart[i] = incl - v;      // exclusive within block
    if (t == SCAN_BLK - 1) g_bsum[blockIdx.x] = incl;  // block total
}

// ---------------- scan of block sums (98 values, one tiny block) ----------------
__global__ __launch_bounds__(128) void scan_bsum_kernel() {
    __shared__ unsigned s[128];
    int t = threadIdx.x;
    unsigned v = (t < N_SBLK) ? g_bsum[t] : 0u;
    s[t] = v;
    __syncthreads();
    for (int o = 1; o < 128; o <<= 1) {
        unsigned n = (t >= o) ? s[t - o] : 0u;
        __syncthreads();
        s[t] += n;
        __syncthreads();
    }
    if (t < N_SBLK) g_bsum[t] = s[t] - v;   // exclusive
}

// ---------------- add block offsets + dinv + reset cursors ----------------
__global__ __launch_bounds__(SCAN_BLK) void add_off_kernel() {
    int i = blockIdx.x * SCAN_BLK + threadIdx.x;
    if (i < N_NODE) {
        g_rowstart[i] += g_bsum[blockIdx.x];
        unsigned c = g_cnt[i];
        g_dinv[i] = rsqrtf(c ? (float)c : 1.0f);
        g_cnt[i] = 0u;
    }
}

// ---------------- scatter edges into CSR with normalized weights ----------------
__global__ __launch_bounds__(256) void scatter_kernel(const int* __restrict__ ei,
                                                       const float* __restrict__ attr) {
    unsigned e = blockIdx.x * blockDim.x + threadIdx.x;
    if (e >= N_EDGE) return;
    int r = ei[e];
    int c = ei[e + N_EDGE];
    float v = g_dinv[r] * attr[e] * g_dinv[c];
    unsigned pos = g_rowstart[r] + atomicAdd(&g_cnt[r], 1u);
    g_colS[pos] = c;
    g_valS[pos] = v;
}

// ---------------- CSR SpMM: 16 threads per row, float4 per thread ----------------
// stage 0: x -> g_y[0];  stage 1: g_y[0] -> g_y[1].
// Scratch pointers resolved IN DEVICE CODE (host-side refs to __device__
// globals resolve to the host shadow symbol).
__global__ __launch_bounds__(256) void spmm_csr_kernel(const float4* __restrict__ xext,
                                                        int stage) {
    unsigned gid = blockIdx.x * blockDim.x + threadIdx.x;
    unsigned row = gid >> 4;
    if (row >= N_NODE) return;
    unsigned lane = gid & 15u;
    const float4* __restrict__ xin =
        (stage == 0) ? xext : (const float4*)g_y[0];
    float4* yout = (float4*)g_y[stage];

    unsigned s = g_rowstart[row], e = g_rowstart[row + 1];
    float4 acc0 = {0.f, 0.f, 0.f, 0.f};
    float4 acc1 = {0.f, 0.f, 0.f, 0.f};
    unsigned i = s;
    for (; i + 2 <= e; i += 2) {
        int   c0 = __ldg(g_colS + i);
        int   c1 = __ldg(g_colS + i + 1);
        float v0 = __ldg(g_valS + i);
        float v1 = __ldg(g_valS + i + 1);
        float4 x0 = __ldg(xin + (unsigned)c0 * 16u + lane);
        float4 x1 = __ldg(xin + (unsigned)c1 * 16u + lane);
        acc0.x += v0 * x0.x; acc0.y += v0 * x0.y;
        acc0.z += v0 * x0.z; acc0.w += v0 * x0.w;
        acc1.x += v1 * x1.x; acc1.y += v1 * x1.y;
        acc1.z += v1 * x1.z; acc1.w += v1 * x1.w;
    }
    if (i < e) {
        int   c0 = __ldg(g_colS + i);
        float v0 = __ldg(g_valS + i);
        float4 x0 = __ldg(xin + (unsigned)c0 * 16u + lane);
        acc0.x += v0 * x0.x; acc0.y += v0 * x0.y;
        acc0.z += v0 * x0.z; acc0.w += v0 * x0.w;
    }
    acc0.x += acc1.x; acc0.y += acc1.y; acc0.z += acc1.z; acc0.w += acc1.w;
    yout[row * 16u + lane] = acc0;
}

// ---------------- final CSR SpMM (S^3 x) fused with output combine ----------------
// out[n,L,:] = sum_k q[L][k] * (S^k x)[n,:],  out shape (N_NODE, 4, 64) f32
__global__ __launch_bounds__(256) void spmm_final_kernel(const float4* __restrict__ x,
                                                          float4* __restrict__ out) {
    unsigned gid = blockIdx.x * blockDim.x + threadIdx.x;
    unsigned row = gid >> 4;
    if (row >= N_NODE) return;
    unsigned lane = gid & 15u;
    unsigned s = g_rowstart[row], e = g_rowstart[row + 1];
    const float4* __restrict__ y1 = (const float4*)g_y[1];   // S^2 x
    float4 acc0 = {0.f, 0.f, 0.f, 0.f};
    float4 acc1 = {0.f, 0.f, 0.f, 0.f};
    unsigned i = s;
    for (; i + 2 <= e; i += 2) {
        int   c0 = __ldg(g_colS + i);
        int   c1 = __ldg(g_colS + i + 1);
        float v0 = __ldg(g_valS + i);
        float v1 = __ldg(g_valS + i + 1);
        float4 x0 = __ldg(y1 + (unsigned)c0 * 16u + lane);
        float4 x1 = __ldg(y1 + (unsigned)c1 * 16u + lane);
        acc0.x += v0 * x0.x; acc0.y += v0 * x0.y;
        acc0.z += v0 * x0.z; acc0.w += v0 * x0.w;
        acc1.x += v1 * x1.x; acc1.y += v1 * x1.y;
        acc1.z += v1 * x1.z; acc1.w += v1 * x1.w;
    }
    if (i < e) {
        int   c0 = __ldg(g_colS + i);
        float v0 = __ldg(g_valS + i);
        float4 x0 = __ldg(y1 + (unsigned)c0 * 16u + lane);
        acc0.x += v0 * x0.x; acc0.y += v0 * x0.y;
        acc0.z += v0 * x0.z; acc0.w += v0 * x0.w;
    }
    float4 a3;
    a3.x = acc0.x + acc1.x; a3.y = acc0.y + acc1.y;
    a3.z = acc0.z + acc1.z; a3.w = acc0.w + acc1.w;

    unsigned idx = row * 16u + lane;
    float4 x0 = __ldg(x + idx);
    float4 a1 = ((const float4*)g_y[0])[idx];
    float4 a2 = ((const float4*)g_y[1])[idx];

    float q00 = g_q[0];
    float q10 = g_q[4],  q11 = g_q[5];
    float q20 = g_q[8],  q21 = g_q[9],  q22 = g_q[10];
    float q30 = g_q[12], q31 = g_q[13], q32 = g_q[14], q33 = g_q[15];

    float4 o0, o1, o2, o3;
    o0.x = q00 * x0.x; o0.y = q00 * x0.y; o0.z = q00 * x0.z; o0.w = q00 * x0.w;

    o1.x = q10 * x0.x + q11 * a1.x;
    o1.y = q10 * x0.y + q11 * a1.y;
    o1.z = q10 * x0.z + q11 * a1.z;
    o1.w = q10 * x0.w + q11 * a1.w;

    o2.x = q20 * x0.x + q21 * a1.x + q22 * a2.x;
    o2.y = q20 * x0.y + q21 * a1.y + q22 * a2.y;
    o2.z = q20 * x0.z + q21 * a1.z + q22 * a2.z;
    o2.w = q20 * x0.w + q21 * a1.w + q22 * a2.w;

    o3.x = q30 * x0.x + q31 * a1.x + q32 * a2.x + q33 * a3.x;
    o3.y = q30 * x0.y + q31 * a1.y + q32 * a2.y + q33 * a3.y;
    o3.z = q30 * x0.z + q31 * a1.z + q32 * a2.z + q33 * a3.z;
    o3.w = q30 * x0.w + q31 * a1.w + q32 * a2.w + q33 * a3.w;

    unsigned base = row * 64u + lane;
    out[base +  0u] = o0;
    out[base + 16u] = o1;
    out[base + 32u] = o2;
    out[base + 48u] = o3;
}

// ---------------- launch ----------------
extern "C" void kernel_launch(void* const* d_in, const int* in_sizes, int n_in,
                              void* d_out, int out_size) {
    const float* x      = (const float*)d_in[0];
    const int*   ei     = (const int*)  d_in[1];
    const float* attr   = (const float*)d_in[2];
    const float* alphas = (const float*)d_in[3];
    const float* w      = (const float*)d_in[4];
    const float* a_arr  = (const float*)d_in[5];
    const float* b_arr  = (const float*)d_in[6];
    float* out = (float*)d_out;

    zero_cnt_kernel<<<(N_NODE + 255) / 256, 256>>>();
    coeff_kernel<<<1, 32>>>(alphas, w, a_arr, b_arr);
    count_kernel<<<(N_EDGE + 255) / 256, 256>>>(ei);
    block_scan_kernel<<<N_SBLK, SCAN_BLK>>>();
    scan_bsum_kernel<<<1, 128>>>();
    add_off_kernel<<<N_SBLK, SCAN_BLK>>>();
    scatter_kernel<<<(N_EDGE + 255) / 256, 256>>>(ei, attr);

    const unsigned rt = (unsigned)N_NODE * 16u;   // 800k threads
    spmm_csr_kernel<<<(rt + 255) / 256, 256>>>((const float4*)x, 0);
    spmm_csr_kernel<<<(rt + 255) / 256, 256>>>((const float4*)x, 1);
    spmm_final_kernel<<<(rt + 255) / 256, 256>>>((const float4*)x, (float4*)out);
}

// round 5
// speedup vs baseline: 1.5217x; 1.0129x over previous
#include <cuda_runtime.h>

#define N_NODE 50000
#define N_EDGE 800000
#define D_FEAT 64
#define N_M    11
#define DEPTH  3

#define SCAN_BLK 512
#define N_SBLK ((N_NODE + SCAN_BLK - 1) / SCAN_BLK)   // 98

// ---------------- device scratch (no allocations; zero-init at module load) ----
__device__ float    g_y[2][N_NODE * D_FEAT];   // S x, S^2 x
__device__ float    g_dinv[N_NODE];
__device__ unsigned g_cnt[N_NODE];             // counts; scatter drains back to 0
__device__ unsigned g_rowstart[N_NODE + 1];
__device__ unsigned g_bsum[N_SBLK];
__device__ int2     g_csr[N_EDGE];             // packed {col, val bits}, row-sorted
__device__ float    g_q[16];                   // q[L][k]

// ---------------- polynomial coefficient table ----------------
// xs_hist[L][m] = sum_k p[L][m][k] * S^k x  (recurrence linear in S, xs0==x).
// l=-1, r=1 so (l+r)=0, (r-l)=2.
__global__ void coeff_kernel(const float* __restrict__ alphas,
                             const float* __restrict__ w,
                             const float* __restrict__ a_arr,
                             const float* __restrict__ b_arr) {
    if (threadIdx.x != 0 || blockIdx.x != 0) return;
    double q[4][4] = {};
    for (int m = 0; m < N_M; m++) {
        double a = a_arr[m], b = b_arr[m];
        double p[4][4] = {};
        p[0][0] = 1.0;
        double coef1 = (a - b) * 0.5;
        double coef2 = (a + b + 2.0) * 0.5;
        double al0 = alphas[0 * N_M + m];
        p[1][0] = al0 * coef1;
        p[1][1] = al0 * coef2;
        for (int L = 2; L <= DEPTH; L++) {
            double Lf = (double)L;
            double coef_l  = 2.0 * Lf * (Lf + a + b) * (2.0 * Lf - 2.0 + a + b);
            double c_lm1_1 = (2.0 * Lf + a + b - 1.0) * (2.0 * Lf + a + b) * (2.0 * Lf + a + b - 2.0);
            double c_lm1_2 = (2.0 * Lf + a + b - 1.0) * (a * a - b * b);
            double c_lm2   = 2.0 * (Lf - 1.0 + a) * (Lf - 1.0 + b) * (2.0 * Lf + a + b);
            double alL   = alphas[(L - 1) * N_M + m];
            double alLm1 = alphas[(L - 2) * N_M + m];
            double tmp1 = alL * (c_lm1_1 / coef_l);
            double tmp2 = alL * (c_lm1_2 / coef_l);
            double tmp3 = alL * alLm1 * (c_lm2 / coef_l);
            for (int k = 0; k <= L; k++) {
                double t = 0.0;
                if (k > 0) t += tmp1 * p[L - 1][k - 1];
                t -= tmp2 * p[L - 1][k];
                t -= tmp3 * p[L - 2][k];
                p[L][k] = t;
            }
        }
        double wm = w[m];
        for (int L = 0; L < 4; L++)
            for (int k = 0; k < 4; k++)
                q[L][k] += wm * p[L][k];
    }
    for (int i = 0; i < 16; i++) g_q[i] = (float)q[i / 4][i % 4];
}

// ---------------- per-row edge counts ----------------
__global__ __launch_bounds__(256) void count_kernel(const int* __restrict__ ei) {
    unsigned e = blockIdx.x * blockDim.x + threadIdx.x;
    if (e < N_EDGE) atomicAdd(&g_cnt[ei[e]], 1u);
}

// ---------------- two-level exclusive scan: level 1 (per-block) ----------------
__global__ __launch_bounds__(SCAN_BLK) void block_scan_kernel() {
    __shared__ unsigned warp_sums[SCAN_BLK / 32];
    int t = threadIdx.x;
    int i = blockIdx.x * SCAN_BLK + t;
    unsigned v = (i < N_NODE) ? g_cnt[i] : 0u;
    unsigned s = v;
    #pragma unroll
    for (int o = 1; o < 32; o <<= 1) {
        unsigned n = __shfl_up_sync(0xffffffffu, s, o);
        if ((t & 31) >= o) s += n;
    }
    if ((t & 31) == 31) warp_sums[t >> 5] = s;
    __syncthreads();
    if (t < SCAN_BLK / 32) {
        unsigned ws = warp_sums[t];
        #pragma unroll
        for (int o = 1; o < SCAN_BLK / 32; o <<= 1) {
            unsigned n = __shfl_up_sync((1u << (SCAN_BLK / 32)) - 1u, ws, o);
            if (t >= o) ws += n;
        }
        warp_sums[t] = ws;
    }
    __syncthreads();
    unsigned base = (t >= 32) ? warp_sums[(t >> 5) - 1] : 0u;
    unsigned incl = base + s;
    if (i < N_NODE) g_rowstart[i] = incl - v;
    if (t == SCAN_BLK - 1) g_bsum[blockIdx.x] = incl;
}

// ---------------- scan of block sums (98 values, one tiny block) ----------------
__global__ __launch_bounds__(128) void scan_bsum_kernel() {
    __shared__ unsigned s[128];
    int t = threadIdx.x;
    unsigned v = (t < N_SBLK) ? g_bsum[t] : 0u;
    s[t] = v;
    __syncthreads();
    for (int o = 1; o < 128; o <<= 1) {
        unsigned n = (t >= o) ? s[t - o] : 0u;
        __syncthreads();
        s[t] += n;
        __syncthreads();
    }
    if (t < N_SBLK) g_bsum[t] = s[t] - v;   // exclusive
    if (t == 0) g_rowstart[N_NODE] = N_EDGE;
}

// ---------------- add block offsets + dinv (counters left intact) ----------------
__global__ __launch_bounds__(SCAN_BLK) void add_off_kernel() {
    int i = blockIdx.x * SCAN_BLK + threadIdx.x;
    if (i < N_NODE) {
        g_rowstart[i] += g_bsum[blockIdx.x];
        unsigned c = g_cnt[i];
        g_dinv[i] = rsqrtf(c ? (float)c : 1.0f);
    }
}

// ---------------- scatter edges into packed CSR ----------------
// atomicSub drains g_cnt back to 0, restoring the pre-launch state so the
// next graph replay's count_kernel starts from zeros (no zeroing pass needed;
// __device__ globals are zero-initialized at module load for the first call).
__global__ __launch_bounds__(256) void scatter_kernel(const int* __restrict__ ei,
                                                       const float* __restrict__ attr) {
    unsigned e = blockIdx.x * blockDim.x + threadIdx.x;
    if (e >= N_EDGE) return;
    int r = ei[e];
    int c = ei[e + N_EDGE];
    float v = g_dinv[r] * attr[e] * g_dinv[c];
    unsigned old = atomicSub(&g_cnt[r], 1u);
    unsigned pos = g_rowstart[r] + old - 1u;
    g_csr[pos] = make_int2(c, __float_as_int(v));
}

// ---------------- CSR SpMM: 16 threads/row, float4/thread, 4-way unroll ------
// stage 0: x -> g_y[0];  stage 1: g_y[0] -> g_y[1].
// Scratch pointers resolved IN DEVICE CODE (host-side refs to __device__
// globals resolve to the host shadow symbol).
__global__ __launch_bounds__(256) void spmm_csr_kernel(const float4* __restrict__ xext,
                                                        int stage) {
    unsigned gid = blockIdx.x * blockDim.x + threadIdx.x;
    unsigned row = gid >> 4;
    if (row >= N_NODE) return;
    unsigned lane = gid & 15u;
    const float4* __restrict__ xin =
        (stage == 0) ? xext : (const float4*)g_y[0];
    float4* yout = (float4*)g_y[stage];

    unsigned s = g_rowstart[row], e = g_rowstart[row + 1];
    float4 acc0 = {0.f,0.f,0.f,0.f}, acc1 = {0.f,0.f,0.f,0.f};
    float4 acc2 = {0.f,0.f,0.f,0.f}, acc3 = {0.f,0.f,0.f,0.f};
    unsigned i = s;
    for (; i + 4 <= e; i += 4) {
        int2 p0 = __ldg(g_csr + i);
        int2 p1 = __ldg(g_csr + i + 1);
        int2 p2 = __ldg(g_csr + i + 2);
        int2 p3 = __ldg(g_csr + i + 3);
        float4 x0 = __ldg(xin + (unsigned)p0.x * 16u + lane);
        float4 x1 = __ldg(xin + (unsigned)p1.x * 16u + lane);
        float4 x2 = __ldg(xin + (unsigned)p2.x * 16u + lane);
        float4 x3 = __ldg(xin + (unsigned)p3.x * 16u + lane);
        float v0 = __int_as_float(p0.y), v1 = __int_as_float(p1.y);
        float v2 = __int_as_float(p2.y), v3 = __int_as_float(p3.y);
        acc0.x += v0*x0.x; acc0.y += v0*x0.y; acc0.z += v0*x0.z; acc0.w += v0*x0.w;
        acc1.x += v1*x1.x; acc1.y += v1*x1.y; acc1.z += v1*x1.z; acc1.w += v1*x1.w;
        acc2.x += v2*x2.x; acc2.y += v2*x2.y; acc2.z += v2*x2.z; acc2.w += v2*x2.w;
        acc3.x += v3*x3.x; acc3.y += v3*x3.y; acc3.z += v3*x3.z; acc3.w += v3*x3.w;
    }
    for (; i < e; i++) {
        int2 p0 = __ldg(g_csr + i);
        float4 x0 = __ldg(xin + (unsigned)p0.x * 16u + lane);
        float v0 = __int_as_float(p0.y);
        acc0.x += v0*x0.x; acc0.y += v0*x0.y; acc0.z += v0*x0.z; acc0.w += v0*x0.w;
    }
    acc0.x += acc1.x + acc2.x + acc3.x;
    acc0.y += acc1.y + acc2.y + acc3.y;
    acc0.z += acc1.z + acc2.z + acc3.z;
    acc0.w += acc1.w + acc2.w + acc3.w;
    yout[row * 16u + lane] = acc0;
}

// ---------------- final CSR SpMM (S^3 x) fused with output combine ----------------
// out[n,L,:] = sum_k q[L][k] * (S^k x)[n,:],  out shape (N_NODE, 4, 64) f32
__global__ __launch_bounds__(256) void spmm_final_kernel(const float4* __restrict__ x,
                                                          float4* __restrict__ out) {
    unsigned gid = blockIdx.x * blockDim.x + threadIdx.x;
    unsigned row = gid >> 4;
    if (row >= N_NODE) return;
    unsigned lane = gid & 15u;
    unsigned s = g_rowstart[row], e = g_rowstart[row + 1];
    const float4* __restrict__ y1 = (const float4*)g_y[1];   // S^2 x
    float4 acc0 = {0.f,0.f,0.f,0.f}, acc1 = {0.f,0.f,0.f,0.f};
    float4 acc2 = {0.f,0.f,0.f,0.f}, acc3 = {0.f,0.f,0.f,0.f};
    unsigned i = s;
    for (; i + 4 <= e; i += 4) {
        int2 p0 = __ldg(g_csr + i);
        int2 p1 = __ldg(g_csr + i + 1);
        int2 p2 = __ldg(g_csr + i + 2);
        int2 p3 = __ldg(g_csr + i + 3);
        float4 x0 = __ldg(y1 + (unsigned)p0.x * 16u + lane);
        float4 x1 = __ldg(y1 + (unsigned)p1.x * 16u + lane);
        float4 x2 = __ldg(y1 + (unsigned)p2.x * 16u + lane);
        float4 x3 = __ldg(y1 + (unsigned)p3.x * 16u + lane);
        float v0 = __int_as_float(p0.y), v1 = __int_as_float(p1.y);
        float v2 = __int_as_float(p2.y), v3 = __int_as_float(p3.y);
        acc0.x += v0*x0.x; acc0.y += v0*x0.y; acc0.z += v0*x0.z; acc0.w += v0*x0.w;
        acc1.x += v1*x1.x; acc1.y += v1*x1.y; acc1.z += v1*x1.z; acc1.w += v1*x1.w;
        acc2.x += v2*x2.x; acc2.y += v2*x2.y; acc2.z += v2*x2.z; acc2.w += v2*x2.w;
        acc3.x += v3*x3.x; acc3.y += v3*x3.y; acc3.z += v3*x3.z; acc3.w += v3*x3.w;
    }
    for (; i < e; i++) {
        int2 p0 = __ldg(g_csr + i);
        float4 x0 = __ldg(y1 + (unsigned)p0.x * 16u + lane);
        float v0 = __int_as_float(p0.y);
        acc0.x += v0*x0.x; acc0.y += v0*x0.y; acc0.z += v0*x0.z; acc0.w += v0*x0.w;
    }
    float4 a3;
    a3.x = acc0.x + acc1.x + acc2.x + acc3.x;
    a3.y = acc0.y + acc1.y + acc2.y + acc3.y;
    a3.z = acc0.z + acc1.z + acc2.z + acc3.z;
    a3.w = acc0.w + acc1.w + acc2.w + acc3.w;

    unsigned idx = row * 16u + lane;
    float4 x0 = __ldg(x + idx);
    float4 a1 = ((const float4*)g_y[0])[idx];
    float4 a2 = ((const float4*)g_y[1])[idx];

    float q00 = g_q[0];
    float q10 = g_q[4],  q11 = g_q[5];
    float q20 = g_q[8],  q21 = g_q[9],  q22 = g_q[10];
    float q30 = g_q[12], q31 = g_q[13], q32 = g_q[14], q33 = g_q[15];

    float4 o0, o1, o2, o3;
    o0.x = q00*x0.x; o0.y = q00*x0.y; o0.z = q00*x0.z; o0.w = q00*x0.w;

    o1.x = q10*x0.x + q11*a1.x;
    o1.y = q10*x0.y + q11*a1.y;
    o1.z = q10*x0.z + q11*a1.z;
    o1.w = q10*x0.w + q11*a1.w;

    o2.x = q20*x0.x + q21*a1.x + q22*a2.x;
    o2.y = q20*x0.y + q21*a1.y + q22*a2.y;
    o2.z = q20*x0.z + q21*a1.z + q22*a2.z;
    o2.w = q20*x0.w + q21*a1.w + q22*a2.w;

    o3.x = q30*x0.x + q31*a1.x + q32*a2.x + q33*a3.x;
    o3.y = q30*x0.y + q31*a1.y + q32*a2.y + q33*a3.y;
    o3.z = q30*x0.z + q31*a1.z + q32*a2.z + q33*a3.z;
    o3.w = q30*x0.w + q31*a1.w + q32*a2.w + q33*a3.w;

    unsigned base = row * 64u + lane;
    out[base +  0u] = o0;
    out[base + 16u] = o1;
    out[base + 32u] = o2;
    out[base + 48u] = o3;
}

// ---------------- launch ----------------
extern "C" void kernel_launch(void* const* d_in, const int* in_sizes, int n_in,
                              void* d_out, int out_size) {
    const float* x      = (const float*)d_in[0];
    const int*   ei     = (const int*)  d_in[1];
    const float* attr   = (const float*)d_in[2];
    const float* alphas = (const float*)d_in[3];
    const float* w      = (const float*)d_in[4];
    const float* a_arr  = (const float*)d_in[5];
    const float* b_arr  = (const float*)d_in[6];
    float* out = (float*)d_out;

    coeff_kernel<<<1, 32>>>(alphas, w, a_arr, b_arr);
    count_kernel<<<(N_EDGE + 255) / 256, 256>>>(ei);
    block_scan_kernel<<<N_SBLK, SCAN_BLK>>>();
    scan_bsum_kernel<<<1, 128>>>();
    add_off_kernel<<<N_SBLK, SCAN_BLK>>>();
    scatter_kernel<<<(N_EDGE + 255) / 256, 256>>>(ei, attr);

    const unsigned rt = (unsigned)N_NODE * 16u;   // 800k threads
    spmm_csr_kernel<<<(rt + 255) / 256, 256>>>((const float4*)x, 0);
    spmm_csr_kernel<<<(rt + 255) / 256, 256>>>((const float4*)x, 1);
    spmm_final_kernel<<<(rt + 255) / 256, 256>>>((const float4*)x, (float4*)out);
}